// round 1
// baseline (speedup 1.0000x reference)
#include <cuda_runtime.h>
#include <cuda_fp16.h>

// ---------------- problem constants ----------------
#define GG   33
#define G3   35937            // 33^3
#define KK   8
#define RR   8
#define NB   4
#define HL   256
#define WL   256
#define HF   1080
#define WF   1920
#define NPIX (HF*WF)          // 2,073,600
#define OUT_IMG (NB*3*NPIX)   // 24,883,200

// d_out layout: out | alpha | delta | L | delta_norm  (all float32, concatenated)
#define ALPHA_OFF OUT_IMG
#define DELTA_SZ  (NB*G3*3)            // 431,244
#define DELTA_OFF (ALPHA_OFF + 32)
#define L_OFF     (DELTA_OFF + DELTA_SZ)
#define NORM_OFF  (L_OFF + DELTA_SZ)

#define TRI_SMEM (G3*4 + G3*2 + 16)    // half2 rg[G3] + half b[G3]

// ---------------- device scratch (no allocations allowed) ----------------
__device__ float g_s1[2*NB*16*128*128];   // conv1 outputs, both encoders (8.4 MB)
__device__ float g_hsum[2*NB*32];         // conv2+relu spatial sums
__device__ float g_alpha[NB*KK];
__device__ float g_u[NB*RR*GG];
__device__ float g_v[NB*RR*GG];
__device__ float g_w[NB*RR*GG];
__device__ float g_c[NB*RR*3];
__device__ float g_norm;

// ============================================================
// K1: conv1 (3->16, 3x3, stride2, pad1) + relu, both encoders
// grid: 512 blocks x 256 thr. thread = one spatial output, all 16 couts.
// ============================================================
__global__ void __launch_bounds__(256) conv1_kernel(
    const float* __restrict__ img_lr,
    const float* __restrict__ w_wp, const float* __restrict__ b_wp,
    const float* __restrict__ w_rp, const float* __restrict__ b_rp)
{
    __shared__ float ws[432];
    __shared__ float bs[16];
    int blk = blockIdx.x;          // 0..511
    int e   = blk >> 8;            // encoder: 0=wp 1=rp
    int rem = blk & 255;
    int b   = rem >> 6;
    int tile= rem & 63;
    const float* w  = e ? w_rp : w_wp;
    const float* bi = e ? b_rp : b_wp;
    int tid = threadIdx.x;
    for (int i = tid; i < 432; i += 256) ws[i] = w[i];  // OIHW contiguous
    if (tid < 16) bs[tid] = bi[tid];
    if (blk == 0) g_hsum[tid] = 0.f;   // zero for K2 atomics (256 entries)
    __syncthreads();

    int pix = tile*256 + tid;
    int oh = pix >> 7, ow = pix & 127;
    float in[27];
    #pragma unroll
    for (int ci = 0; ci < 3; ci++)
      #pragma unroll
      for (int kh = 0; kh < 3; kh++)
        #pragma unroll
        for (int kw = 0; kw < 3; kw++) {
            int ih = 2*oh - 1 + kh, iw = 2*ow - 1 + kw;
            float v = 0.f;
            if (ih >= 0 && ih < HL && iw >= 0 && iw < WL)
                v = img_lr[((b*3 + ci)*HL + ih)*WL + iw];
            in[ci*9 + kh*3 + kw] = v;
        }
    float acc[16];
    #pragma unroll
    for (int co = 0; co < 16; co++) acc[co] = bs[co];
    #pragma unroll
    for (int j = 0; j < 27; j++) {
        float v = in[j];
        #pragma unroll
        for (int co = 0; co < 16; co++) acc[co] = fmaf(v, ws[co*27 + j], acc[co]);
    }
    float* outp = g_s1 + (size_t)(e*NB + b)*16*16384 + pix;
    #pragma unroll
    for (int co = 0; co < 16; co++) outp[co*16384] = fmaxf(acc[co], 0.f);
}

// ============================================================
// K2: conv2 (16->32, 3x3, stride2, pad1) + relu + spatial-sum (mean later)
// grid: 128 blocks x 256 thr. thread = one spatial output, all 32 couts.
// ============================================================
__global__ void __launch_bounds__(256) conv2_kernel(
    const float* __restrict__ w_wp, const float* __restrict__ b_wp,
    const float* __restrict__ w_rp, const float* __restrict__ b_rp)
{
    __shared__ float ws[4608];   // [(ci*9+k)*32 + co]
    __shared__ float bs[32];
    __shared__ float red[8*32];
    int blk = blockIdx.x;        // 0..127
    int e   = blk >> 6;
    int b   = (blk >> 4) & 3;
    int tile= blk & 15;
    const float* w  = e ? w_rp : w_wp;
    const float* bi = e ? b_rp : b_wp;
    int tid = threadIdx.x;
    for (int t = tid; t < 4608; t += 256) {
        int co = t & 31;
        int cik = t >> 5;                   // ci*9 + k
        int ci = cik / 9, k = cik - ci*9;
        ws[t] = w[(co*16 + ci)*9 + k];
    }
    if (tid < 32) bs[tid] = bi[tid];
    __syncthreads();

    int pix = tile*256 + tid;               // 0..4095
    int oh = pix >> 6, ow = pix & 63;
    const float* inp = g_s1 + (size_t)(e*NB + b)*16*16384;
    float acc[32];
    #pragma unroll
    for (int co = 0; co < 32; co++) acc[co] = 0.f;
    for (int ci = 0; ci < 16; ci++) {
        float v9[9];
        #pragma unroll
        for (int kh = 0; kh < 3; kh++)
          #pragma unroll
          for (int kw = 0; kw < 3; kw++) {
              int ih = 2*oh - 1 + kh, iw = 2*ow - 1 + kw;
              float v = 0.f;
              if (ih >= 0 && ih < 128 && iw >= 0 && iw < 128)
                  v = inp[ci*16384 + ih*128 + iw];
              v9[kh*3 + kw] = v;
          }
        #pragma unroll
        for (int k = 0; k < 9; k++) {
            float v = v9[k];
            const float* wrow = &ws[(ci*9 + k)*32];
            #pragma unroll
            for (int co = 0; co < 32; co++) acc[co] = fmaf(v, wrow[co], acc[co]);
        }
    }
    int lane = tid & 31, wid = tid >> 5;
    #pragma unroll
    for (int co = 0; co < 32; co++) {
        float v = fmaxf(acc[co] + bs[co], 0.f);   // relu BEFORE mean
        v += __shfl_down_sync(0xffffffffu, v, 16);
        v += __shfl_down_sync(0xffffffffu, v, 8);
        v += __shfl_down_sync(0xffffffffu, v, 4);
        v += __shfl_down_sync(0xffffffffu, v, 2);
        v += __shfl_down_sync(0xffffffffu, v, 1);
        if (lane == 0) red[wid*32 + co] = v;
    }
    __syncthreads();
    if (tid < 32) {
        float s = 0.f;
        #pragma unroll
        for (int w8 = 0; w8 < 8; w8++) s += red[w8*32 + tid];
        atomicAdd(&g_hsum[(e*NB + b)*32 + tid], s);
    }
}

// ============================================================
// K3: FC heads. 1 block x 256 thr.
// ============================================================
__global__ void fc_kernel(
    const float* __restrict__ wp_fc_w, const float* __restrict__ wp_fc_b,
    const float* __restrict__ fcu_w,  const float* __restrict__ fcu_b,
    const float* __restrict__ fcv_w,  const float* __restrict__ fcv_b,
    const float* __restrict__ fcw_w,  const float* __restrict__ fcw_b,
    const float* __restrict__ fcc_w,  const float* __restrict__ fcc_b,
    float* __restrict__ d_out)
{
    __shared__ float h[2*NB*32];
    int tid = threadIdx.x;
    h[tid] = g_hsum[tid] * (1.f/4096.f);     // mean over 64x64
    if (tid == 0) g_norm = 0.f;
    __syncthreads();

    if (tid < NB*KK) {                        // alpha (wp encoder = h[0..127])
        int b = tid >> 3, k = tid & 7;
        float s = wp_fc_b[k];
        const float* hb = &h[b*32];
        #pragma unroll
        for (int i = 0; i < 32; i++) s = fmaf(hb[i], wp_fc_w[k*32 + i], s);
        g_alpha[tid] = s;
        d_out[ALPHA_OFF + tid] = s;
    }
    for (int j = tid; j < NB*RR*GG; j += 256) {   // u,v,w (rp encoder)
        int b = j / (RR*GG), jj = j - b*(RR*GG);
        const float* hb = &h[(NB + b)*32];
        float su = fcu_b[jj], sv = fcv_b[jj], sw = fcw_b[jj];
        #pragma unroll
        for (int i = 0; i < 32; i++) {
            float hv = hb[i];
            su = fmaf(hv, fcu_w[jj*32 + i], su);
            sv = fmaf(hv, fcv_w[jj*32 + i], sv);
            sw = fmaf(hv, fcw_w[jj*32 + i], sw);
        }
        g_u[j] = su; g_v[j] = sv; g_w[j] = sw;
    }
    for (int j = tid; j < NB*RR*3; j += 256) {    // c
        int b = j / (RR*3), jj = j - b*(RR*3);
        const float* hb = &h[(NB + b)*32];
        float s = fcc_b[jj];
        #pragma unroll
        for (int i = 0; i < 32; i++) s = fmaf(hb[i], fcc_w[jj*32 + i], s);
        g_c[j] = s;
    }
}

// ============================================================
// K4: delta (rank-R CP) + L = alpha@bases + delta, |delta| accumulation
// ============================================================
__global__ void __launch_bounds__(256) delta_kernel(
    const float* __restrict__ bases, float* __restrict__ d_out)
{
    int i = blockIdx.x*256 + threadIdx.x;
    float local = 0.f;
    if (i < NB*G3) {
        int b = i / G3, n = i - b*G3;
        int x = n / 1089, rem = n - x*1089;
        int y = rem / 33, z = rem - y*33;
        float d0 = 0.f, d1 = 0.f, d2 = 0.f;
        #pragma unroll
        for (int r = 0; r < RR; r++) {
            int o = b*RR + r;
            float p = g_u[o*GG + x] * g_v[o*GG + y] * g_w[o*GG + z];
            d0 = fmaf(p, g_c[o*3 + 0], d0);
            d1 = fmaf(p, g_c[o*3 + 1], d1);
            d2 = fmaf(p, g_c[o*3 + 2], d2);
        }
        float l0 = d0, l1 = d1, l2 = d2;
        #pragma unroll
        for (int k = 0; k < KK; k++) {
            float a = g_alpha[b*KK + k];
            const float* bp = bases + ((size_t)k*G3 + n)*3;
            l0 = fmaf(a, bp[0], l0);
            l1 = fmaf(a, bp[1], l1);
            l2 = fmaf(a, bp[2], l2);
        }
        size_t off = (size_t)i*3;
        d_out[DELTA_OFF + off    ] = d0;
        d_out[DELTA_OFF + off + 1] = d1;
        d_out[DELTA_OFF + off + 2] = d2;
        d_out[L_OFF + off    ] = l0;
        d_out[L_OFF + off + 1] = l1;
        d_out[L_OFF + off + 2] = l2;
        local = fabsf(d0) + fabsf(d1) + fabsf(d2);
    }
    local += __shfl_down_sync(0xffffffffu, local, 16);
    local += __shfl_down_sync(0xffffffffu, local, 8);
    local += __shfl_down_sync(0xffffffffu, local, 4);
    local += __shfl_down_sync(0xffffffffu, local, 2);
    local += __shfl_down_sync(0xffffffffu, local, 1);
    if ((threadIdx.x & 31) == 0) atomicAdd(&g_norm, local);
}

// ============================================================
// K5: trilinear LUT apply. 148 persistent CTAs (37 per batch), 512 thr,
// full per-batch LUT in smem as fp16 (half2{r,g} + half{b} = 215.6 KB).
// ============================================================
__device__ __forceinline__ void lut1(
    float r, float g, float bb,
    const __half2* __restrict__ smRG, const __half* __restrict__ smB,
    float& o0, float& o1, float& o2)
{
    float x = fminf(fmaxf(r  * 32.f, 0.f), 32.f - 1e-6f);
    float y = fminf(fmaxf(g  * 32.f, 0.f), 32.f - 1e-6f);
    float z = fminf(fmaxf(bb * 32.f, 0.f), 32.f - 1e-6f);
    int ix = (int)x, iy = (int)y, iz = (int)z;
    float fx = x - (float)ix, fy = y - (float)iy, fz = z - (float)iz;
    int base = (ix*33 + iy)*33 + iz;
    float wx0 = 1.f - fx, wy0 = 1.f - fy, wz0 = 1.f - fz;
    float a00 = wx0*wy0, a01 = wx0*fy, a10 = fx*wy0, a11 = fx*fy;
    float w[8] = { a00*wz0, a00*fz, a01*wz0, a01*fz,
                   a10*wz0, a10*fz, a11*wz0, a11*fz };
    const int off[8] = {0, 1, 33, 34, 1089, 1090, 1122, 1123};
    float s0 = 0.f, s1 = 0.f, s2 = 0.f;
    #pragma unroll
    for (int j = 0; j < 8; j++) {
        int idx = base + off[j];
        float2 f = __half22float2(smRG[idx]);
        float fb = __half2float(smB[idx]);
        s0 = fmaf(w[j], f.x, s0);
        s1 = fmaf(w[j], f.y, s1);
        s2 = fmaf(w[j], fb, s2);
    }
    o0 = s0; o1 = s1; o2 = s2;
}

__global__ void __launch_bounds__(512) trilerp_kernel(
    const float* __restrict__ img, float* __restrict__ d_out)
{
    extern __shared__ __align__(16) char smem[];
    __half2* smRG = (__half2*)smem;
    __half*  smB  = (__half*)(smem + (size_t)G3*4);
    int b  = blockIdx.x / 37;
    int bb = blockIdx.x % 37;
    int tid = threadIdx.x;
    if (blockIdx.x == 0 && tid == 0)
        d_out[NORM_OFF] = g_norm * (1.f / (float)(NB*G3*3));

    const float* Lp = d_out + L_OFF + (size_t)b*G3*3;
    for (int n = tid; n < G3; n += 512) {
        float r  = Lp[n*3], g = Lp[n*3 + 1], v = Lp[n*3 + 2];
        smRG[n] = __floats2half2_rn(r, g);
        smB[n]  = __float2half_rn(v);
    }
    __syncthreads();

    const float4* Rp = (const float4*)(img + (size_t)(b*3 + 0)*NPIX);
    const float4* Gp = (const float4*)(img + (size_t)(b*3 + 1)*NPIX);
    const float4* Bp = (const float4*)(img + (size_t)(b*3 + 2)*NPIX);
    float4* oR = (float4*)(d_out + (size_t)(b*3 + 0)*NPIX);
    float4* oG = (float4*)(d_out + (size_t)(b*3 + 1)*NPIX);
    float4* oB = (float4*)(d_out + (size_t)(b*3 + 2)*NPIX);

    const int NQ = NPIX/4;
    for (int q = bb*512 + tid; q < NQ; q += 37*512) {
        float4 r4 = Rp[q], g4 = Gp[q], b4 = Bp[q];
        float4 o0, o1, o2;
        lut1(r4.x, g4.x, b4.x, smRG, smB, o0.x, o1.x, o2.x);
        lut1(r4.y, g4.y, b4.y, smRG, smB, o0.y, o1.y, o2.y);
        lut1(r4.z, g4.z, b4.z, smRG, smB, o0.z, o1.z, o2.z);
        lut1(r4.w, g4.w, b4.w, smRG, smB, o0.w, o1.w, o2.w);
        oR[q] = o0; oG[q] = o1; oB[q] = o2;
    }
}

// ============================================================
// launch
// ============================================================
extern "C" void kernel_launch(void* const* d_in, const int* in_sizes, int n_in,
                              void* d_out_v, int out_size)
{
    const float* img_lr   = (const float*)d_in[0];
    const float* img_full = (const float*)d_in[1];
    const float* bases    = (const float*)d_in[2];
    const float* wp_c1_w  = (const float*)d_in[3];
    const float* wp_c1_b  = (const float*)d_in[4];
    const float* wp_c2_w  = (const float*)d_in[5];
    const float* wp_c2_b  = (const float*)d_in[6];
    const float* wp_fc_w  = (const float*)d_in[7];
    const float* wp_fc_b  = (const float*)d_in[8];
    const float* rp_c1_w  = (const float*)d_in[9];
    const float* rp_c1_b  = (const float*)d_in[10];
    const float* rp_c2_w  = (const float*)d_in[11];
    const float* rp_c2_b  = (const float*)d_in[12];
    const float* rp_fcu_w = (const float*)d_in[13];
    const float* rp_fcu_b = (const float*)d_in[14];
    const float* rp_fcv_w = (const float*)d_in[15];
    const float* rp_fcv_b = (const float*)d_in[16];
    const float* rp_fcw_w = (const float*)d_in[17];
    const float* rp_fcw_b = (const float*)d_in[18];
    const float* rp_fcc_w = (const float*)d_in[19];
    const float* rp_fcc_b = (const float*)d_in[20];
    float* d_out = (float*)d_out_v;

    cudaFuncSetAttribute(trilerp_kernel,
                         cudaFuncAttributeMaxDynamicSharedMemorySize, TRI_SMEM);

    conv1_kernel<<<512, 256>>>(img_lr, wp_c1_w, wp_c1_b, rp_c1_w, rp_c1_b);
    conv2_kernel<<<128, 256>>>(wp_c2_w, wp_c2_b, rp_c2_w, rp_c2_b);
    fc_kernel<<<1, 256>>>(wp_fc_w, wp_fc_b,
                          rp_fcu_w, rp_fcu_b, rp_fcv_w, rp_fcv_b,
                          rp_fcw_w, rp_fcw_b, rp_fcc_w, rp_fcc_b, d_out);
    delta_kernel<<<(NB*G3 + 255)/256, 256>>>(bases, d_out);
    trilerp_kernel<<<148, 512, TRI_SMEM>>>(img_full, d_out);
}

// round 2
// speedup vs baseline: 1.0831x; 1.0831x over previous
#include <cuda_runtime.h>
#include <cuda_fp16.h>

// ---------------- problem constants ----------------
#define GG   33
#define G3   35937            // 33^3
#define KK   8
#define RR   8
#define NB   4
#define HL   256
#define WL   256
#define HF   1080
#define WF   1920
#define NPIX (HF*WF)          // 2,073,600
#define OUT_IMG (NB*3*NPIX)   // 24,883,200

// d_out layout: out | alpha | delta | L | delta_norm  (all float32, concatenated)
#define ALPHA_OFF OUT_IMG
#define DELTA_SZ  (NB*G3*3)            // 431,244
#define DELTA_OFF (ALPHA_OFF + 32)
#define L_OFF     (DELTA_OFF + DELTA_SZ)
#define NORM_OFF  (L_OFF + DELTA_SZ)

#define TRI_SMEM (G3*4 + G3*2 + 16)    // half2 rg[G3] + half b[G3] = 215.6 KB

// ---------------- device scratch (no allocations allowed) ----------------
__device__ float g_s1[2*NB*16*128*128];   // conv1 outputs, both encoders (8.4 MB)
__device__ float g_hsum[2*NB*32];         // conv2+relu spatial sums
__device__ float g_alpha[NB*KK];
__device__ float g_u[NB*RR*GG];
__device__ float g_v[NB*RR*GG];
__device__ float g_w[NB*RR*GG];
__device__ float g_c[NB*RR*3];
__device__ float g_norm;

// ============================================================
// K1: conv1 (3->16, 3x3, stride2, pad1) + relu, both encoders
// ============================================================
__global__ void __launch_bounds__(256) conv1_kernel(
    const float* __restrict__ img_lr,
    const float* __restrict__ w_wp, const float* __restrict__ b_wp,
    const float* __restrict__ w_rp, const float* __restrict__ b_rp)
{
    __shared__ float ws[432];
    __shared__ float bs[16];
    int blk = blockIdx.x;          // 0..511
    int e   = blk >> 8;            // encoder: 0=wp 1=rp
    int rem = blk & 255;
    int b   = rem >> 6;
    int tile= rem & 63;
    const float* w  = e ? w_rp : w_wp;
    const float* bi = e ? b_rp : b_wp;
    int tid = threadIdx.x;
    for (int i = tid; i < 432; i += 256) ws[i] = w[i];
    if (tid < 16) bs[tid] = bi[tid];
    if (blk == 0) g_hsum[tid] = 0.f;
    __syncthreads();

    int pix = tile*256 + tid;
    int oh = pix >> 7, ow = pix & 127;
    float in[27];
    #pragma unroll
    for (int ci = 0; ci < 3; ci++)
      #pragma unroll
      for (int kh = 0; kh < 3; kh++)
        #pragma unroll
        for (int kw = 0; kw < 3; kw++) {
            int ih = 2*oh - 1 + kh, iw = 2*ow - 1 + kw;
            float v = 0.f;
            if (ih >= 0 && ih < HL && iw >= 0 && iw < WL)
                v = img_lr[((b*3 + ci)*HL + ih)*WL + iw];
            in[ci*9 + kh*3 + kw] = v;
        }
    float acc[16];
    #pragma unroll
    for (int co = 0; co < 16; co++) acc[co] = bs[co];
    #pragma unroll
    for (int j = 0; j < 27; j++) {
        float v = in[j];
        #pragma unroll
        for (int co = 0; co < 16; co++) acc[co] = fmaf(v, ws[co*27 + j], acc[co]);
    }
    float* outp = g_s1 + (size_t)(e*NB + b)*16*16384 + pix;
    #pragma unroll
    for (int co = 0; co < 16; co++) outp[co*16384] = fmaxf(acc[co], 0.f);
}

// ============================================================
// K2: conv2 (16->32, 3x3, stride2, pad1) + relu + spatial-sum
// ============================================================
__global__ void __launch_bounds__(256) conv2_kernel(
    const float* __restrict__ w_wp, const float* __restrict__ b_wp,
    const float* __restrict__ w_rp, const float* __restrict__ b_rp)
{
    __shared__ float ws[4608];   // [(ci*9+k)*32 + co]
    __shared__ float bs[32];
    __shared__ float red[8*32];
    int blk = blockIdx.x;        // 0..127
    int e   = blk >> 6;
    int b   = (blk >> 4) & 3;
    int tile= blk & 15;
    const float* w  = e ? w_rp : w_wp;
    const float* bi = e ? b_rp : b_wp;
    int tid = threadIdx.x;
    for (int t = tid; t < 4608; t += 256) {
        int co = t & 31;
        int cik = t >> 5;
        int ci = cik / 9, k = cik - ci*9;
        ws[t] = w[(co*16 + ci)*9 + k];
    }
    if (tid < 32) bs[tid] = bi[tid];
    __syncthreads();

    int pix = tile*256 + tid;               // 0..4095
    int oh = pix >> 6, ow = pix & 63;
    const float* inp = g_s1 + (size_t)(e*NB + b)*16*16384;
    float acc[32];
    #pragma unroll
    for (int co = 0; co < 32; co++) acc[co] = 0.f;
    for (int ci = 0; ci < 16; ci++) {
        float v9[9];
        #pragma unroll
        for (int kh = 0; kh < 3; kh++)
          #pragma unroll
          for (int kw = 0; kw < 3; kw++) {
              int ih = 2*oh - 1 + kh, iw = 2*ow - 1 + kw;
              float v = 0.f;
              if (ih >= 0 && ih < 128 && iw >= 0 && iw < 128)
                  v = inp[ci*16384 + ih*128 + iw];
              v9[kh*3 + kw] = v;
          }
        #pragma unroll
        for (int k = 0; k < 9; k++) {
            float v = v9[k];
            const float* wrow = &ws[(ci*9 + k)*32];
            #pragma unroll
            for (int co = 0; co < 32; co++) acc[co] = fmaf(v, wrow[co], acc[co]);
        }
    }
    int lane = tid & 31, wid = tid >> 5;
    #pragma unroll
    for (int co = 0; co < 32; co++) {
        float v = fmaxf(acc[co] + bs[co], 0.f);   // relu BEFORE mean
        v += __shfl_down_sync(0xffffffffu, v, 16);
        v += __shfl_down_sync(0xffffffffu, v, 8);
        v += __shfl_down_sync(0xffffffffu, v, 4);
        v += __shfl_down_sync(0xffffffffu, v, 2);
        v += __shfl_down_sync(0xffffffffu, v, 1);
        if (lane == 0) red[wid*32 + co] = v;
    }
    __syncthreads();
    if (tid < 32) {
        float s = 0.f;
        #pragma unroll
        for (int w8 = 0; w8 < 8; w8++) s += red[w8*32 + tid];
        atomicAdd(&g_hsum[(e*NB + b)*32 + tid], s);
    }
}

// ============================================================
// K3: FC heads. 1 block x 256 thr.
// ============================================================
__global__ void fc_kernel(
    const float* __restrict__ wp_fc_w, const float* __restrict__ wp_fc_b,
    const float* __restrict__ fcu_w,  const float* __restrict__ fcu_b,
    const float* __restrict__ fcv_w,  const float* __restrict__ fcv_b,
    const float* __restrict__ fcw_w,  const float* __restrict__ fcw_b,
    const float* __restrict__ fcc_w,  const float* __restrict__ fcc_b,
    float* __restrict__ d_out)
{
    __shared__ float h[2*NB*32];
    int tid = threadIdx.x;
    h[tid] = g_hsum[tid] * (1.f/4096.f);
    if (tid == 0) g_norm = 0.f;
    __syncthreads();

    if (tid < NB*KK) {                        // alpha (wp encoder)
        int b = tid >> 3, k = tid & 7;
        float s = wp_fc_b[k];
        const float* hb = &h[b*32];
        #pragma unroll
        for (int i = 0; i < 32; i++) s = fmaf(hb[i], wp_fc_w[k*32 + i], s);
        g_alpha[tid] = s;
        d_out[ALPHA_OFF + tid] = s;
    }
    for (int j = tid; j < NB*RR*GG; j += 256) {   // u,v,w (rp encoder)
        int b = j / (RR*GG), jj = j - b*(RR*GG);
        const float* hb = &h[(NB + b)*32];
        float su = fcu_b[jj], sv = fcv_b[jj], sw = fcw_b[jj];
        #pragma unroll
        for (int i = 0; i < 32; i++) {
            float hv = hb[i];
            su = fmaf(hv, fcu_w[jj*32 + i], su);
            sv = fmaf(hv, fcv_w[jj*32 + i], sv);
            sw = fmaf(hv, fcw_w[jj*32 + i], sw);
        }
        g_u[j] = su; g_v[j] = sv; g_w[j] = sw;
    }
    for (int j = tid; j < NB*RR*3; j += 256) {    // c
        int b = j / (RR*3), jj = j - b*(RR*3);
        const float* hb = &h[(NB + b)*32];
        float s = fcc_b[jj];
        #pragma unroll
        for (int i = 0; i < 32; i++) s = fmaf(hb[i], fcc_w[jj*32 + i], s);
        g_c[j] = s;
    }
}

// ============================================================
// K4: delta + L. One thread per grid node n; loop over batches inside
// so bases[k][n][:] is loaded once and reused 4x. u/v/w/c/alpha in smem.
// ============================================================
__global__ void __launch_bounds__(256) delta_kernel(
    const float* __restrict__ bases, float* __restrict__ d_out)
{
    __shared__ float su[NB*RR*GG], sv[NB*RR*GG], sw[NB*RR*GG];
    __shared__ float sc[NB*RR*3];
    __shared__ float sa[NB*KK];
    int tid = threadIdx.x;
    for (int i = tid; i < NB*RR*GG; i += 256) {
        su[i] = g_u[i]; sv[i] = g_v[i]; sw[i] = g_w[i];
    }
    if (tid < NB*RR*3) sc[tid] = g_c[tid];
    if (tid < NB*KK)   sa[tid] = g_alpha[tid];
    __syncthreads();

    int n = blockIdx.x*256 + tid;
    float local = 0.f;
    if (n < G3) {
        int x = n / 1089, rem = n - x*1089;
        int y = rem / 33, z = rem - y*33;
        // stage bases[k][n][0..2] once (reused for all 4 batches)
        float bb[KK][3];
        #pragma unroll
        for (int k = 0; k < KK; k++) {
            const float* bp = bases + ((size_t)k*G3 + n)*3;
            bb[k][0] = bp[0]; bb[k][1] = bp[1]; bb[k][2] = bp[2];
        }
        #pragma unroll
        for (int b = 0; b < NB; b++) {
            float d0 = 0.f, d1 = 0.f, d2 = 0.f;
            #pragma unroll
            for (int r = 0; r < RR; r++) {
                int o = b*RR + r;
                float p = su[o*GG + x] * sv[o*GG + y] * sw[o*GG + z];
                d0 = fmaf(p, sc[o*3 + 0], d0);
                d1 = fmaf(p, sc[o*3 + 1], d1);
                d2 = fmaf(p, sc[o*3 + 2], d2);
            }
            float l0 = d0, l1 = d1, l2 = d2;
            #pragma unroll
            for (int k = 0; k < KK; k++) {
                float a = sa[b*KK + k];
                l0 = fmaf(a, bb[k][0], l0);
                l1 = fmaf(a, bb[k][1], l1);
                l2 = fmaf(a, bb[k][2], l2);
            }
            size_t off = (size_t)(b*G3 + n)*3;
            d_out[DELTA_OFF + off    ] = d0;
            d_out[DELTA_OFF + off + 1] = d1;
            d_out[DELTA_OFF + off + 2] = d2;
            d_out[L_OFF + off    ] = l0;
            d_out[L_OFF + off + 1] = l1;
            d_out[L_OFF + off + 2] = l2;
            local += fabsf(d0) + fabsf(d1) + fabsf(d2);
        }
    }
    local += __shfl_down_sync(0xffffffffu, local, 16);
    local += __shfl_down_sync(0xffffffffu, local, 8);
    local += __shfl_down_sync(0xffffffffu, local, 4);
    local += __shfl_down_sync(0xffffffffu, local, 2);
    local += __shfl_down_sync(0xffffffffu, local, 1);
    if ((threadIdx.x & 31) == 0) atomicAdd(&g_norm, local);
}

// ============================================================
// K5: trilinear LUT apply. 148 CTAs x 1024 thr (32 warps/SM),
// full per-batch LUT in smem as fp16 (half2{r,g} + half{b} = 215.6 KB).
// ============================================================
__device__ __forceinline__ void lut1(
    float r, float g, float bb,
    const __half2* __restrict__ smRG, const __half* __restrict__ smB,
    float& o0, float& o1, float& o2)
{
    float x = fminf(fmaxf(r  * 32.f, 0.f), 32.f - 1e-6f);
    float y = fminf(fmaxf(g  * 32.f, 0.f), 32.f - 1e-6f);
    float z = fminf(fmaxf(bb * 32.f, 0.f), 32.f - 1e-6f);
    int ix = (int)x, iy = (int)y, iz = (int)z;
    float fx = x - (float)ix, fy = y - (float)iy, fz = z - (float)iz;
    int base = (ix*33 + iy)*33 + iz;
    float wx0 = 1.f - fx, wy0 = 1.f - fy, wz0 = 1.f - fz;
    float a00 = wx0*wy0, a01 = wx0*fy, a10 = fx*wy0, a11 = fx*fy;
    float w[8] = { a00*wz0, a00*fz, a01*wz0, a01*fz,
                   a10*wz0, a10*fz, a11*wz0, a11*fz };
    const int off[8] = {0, 1, 33, 34, 1089, 1090, 1122, 1123};
    float s0 = 0.f, s1 = 0.f, s2 = 0.f;
    #pragma unroll
    for (int j = 0; j < 8; j++) {
        int idx = base + off[j];
        float2 f = __half22float2(smRG[idx]);
        float fb = __half2float(smB[idx]);
        s0 = fmaf(w[j], f.x, s0);
        s1 = fmaf(w[j], f.y, s1);
        s2 = fmaf(w[j], fb, s2);
    }
    o0 = s0; o1 = s1; o2 = s2;
}

__global__ void __launch_bounds__(1024, 1) trilerp_kernel(
    const float* __restrict__ img, float* __restrict__ d_out)
{
    extern __shared__ __align__(16) char smem[];
    __half2* smRG = (__half2*)smem;
    __half*  smB  = (__half*)(smem + (size_t)G3*4);
    int b  = blockIdx.x / 37;
    int bb = blockIdx.x % 37;
    int tid = threadIdx.x;
    if (blockIdx.x == 0 && tid == 0)
        d_out[NORM_OFF] = g_norm * (1.f / (float)(NB*G3*3));

    const float* Lp = d_out + L_OFF + (size_t)b*G3*3;
    for (int n = tid; n < G3; n += 1024) {
        float r  = Lp[n*3], g = Lp[n*3 + 1], v = Lp[n*3 + 2];
        smRG[n] = __floats2half2_rn(r, g);
        smB[n]  = __float2half_rn(v);
    }
    __syncthreads();

    const float4* Rp = (const float4*)(img + (size_t)(b*3 + 0)*NPIX);
    const float4* Gp = (const float4*)(img + (size_t)(b*3 + 1)*NPIX);
    const float4* Bp = (const float4*)(img + (size_t)(b*3 + 2)*NPIX);
    float4* oR = (float4*)(d_out + (size_t)(b*3 + 0)*NPIX);
    float4* oG = (float4*)(d_out + (size_t)(b*3 + 1)*NPIX);
    float4* oB = (float4*)(d_out + (size_t)(b*3 + 2)*NPIX);

    const int NQ = NPIX/4;
    for (int q = bb*1024 + tid; q < NQ; q += 37*1024) {
        float4 r4 = Rp[q], g4 = Gp[q], b4 = Bp[q];
        float4 o0, o1, o2;
        lut1(r4.x, g4.x, b4.x, smRG, smB, o0.x, o1.x, o2.x);
        lut1(r4.y, g4.y, b4.y, smRG, smB, o0.y, o1.y, o2.y);
        lut1(r4.z, g4.z, b4.z, smRG, smB, o0.z, o1.z, o2.z);
        lut1(r4.w, g4.w, b4.w, smRG, smB, o0.w, o1.w, o2.w);
        oR[q] = o0; oG[q] = o1; oB[q] = o2;
    }
}

// ============================================================
// launch
// ============================================================
extern "C" void kernel_launch(void* const* d_in, const int* in_sizes, int n_in,
                              void* d_out_v, int out_size)
{
    const float* img_lr   = (const float*)d_in[0];
    const float* img_full = (const float*)d_in[1];
    const float* bases    = (const float*)d_in[2];
    const float* wp_c1_w  = (const float*)d_in[3];
    const float* wp_c1_b  = (const float*)d_in[4];
    const float* wp_c2_w  = (const float*)d_in[5];
    const float* wp_c2_b  = (const float*)d_in[6];
    const float* wp_fc_w  = (const float*)d_in[7];
    const float* wp_fc_b  = (const float*)d_in[8];
    const float* rp_c1_w  = (const float*)d_in[9];
    const float* rp_c1_b  = (const float*)d_in[10];
    const float* rp_c2_w  = (const float*)d_in[11];
    const float* rp_c2_b  = (const float*)d_in[12];
    const float* rp_fcu_w = (const float*)d_in[13];
    const float* rp_fcu_b = (const float*)d_in[14];
    const float* rp_fcv_w = (const float*)d_in[15];
    const float* rp_fcv_b = (const float*)d_in[16];
    const float* rp_fcw_w = (const float*)d_in[17];
    const float* rp_fcw_b = (const float*)d_in[18];
    const float* rp_fcc_w = (const float*)d_in[19];
    const float* rp_fcc_b = (const float*)d_in[20];
    float* d_out = (float*)d_out_v;

    cudaFuncSetAttribute(trilerp_kernel,
                         cudaFuncAttributeMaxDynamicSharedMemorySize, TRI_SMEM);

    conv1_kernel<<<512, 256>>>(img_lr, wp_c1_w, wp_c1_b, rp_c1_w, rp_c1_b);
    conv2_kernel<<<128, 256>>>(wp_c2_w, wp_c2_b, rp_c2_w, rp_c2_b);
    fc_kernel<<<1, 256>>>(wp_fc_w, wp_fc_b,
                          rp_fcu_w, rp_fcu_b, rp_fcv_w, rp_fcv_b,
                          rp_fcw_w, rp_fcw_b, rp_fcc_w, rp_fcc_b, d_out);
    delta_kernel<<<(G3 + 255)/256, 256>>>(bases, d_out);
    trilerp_kernel<<<148, 1024, TRI_SMEM>>>(img_full, d_out);
}

// round 3
// speedup vs baseline: 1.2147x; 1.1215x over previous
#include <cuda_runtime.h>
#include <cuda_fp16.h>

// ---------------- problem constants ----------------
#define GG   33
#define G3   35937            // 33^3
#define KK   8
#define RR   8
#define NB   4
#define HL   256
#define WL   256
#define HF   1080
#define WF   1920
#define NPIX (HF*WF)          // 2,073,600
#define OUT_IMG (NB*3*NPIX)   // 24,883,200

// d_out layout: out | alpha | delta | L | delta_norm  (all float32, concatenated)
#define ALPHA_OFF OUT_IMG
#define DELTA_SZ  (NB*G3*3)            // 431,244
#define DELTA_OFF (ALPHA_OFF + 32)
#define L_OFF     (DELTA_OFF + DELTA_SZ)
#define NORM_OFF  (L_OFF + DELTA_SZ)

#define TRI_SMEM (G3*4 + 16)           // packed uint32 LUT: 143.7 KB

// ---------------- device scratch (no allocations allowed) ----------------
__device__ float g_s1[2*NB*16*128*128];   // conv1 outputs, both encoders
__device__ float g_hsum[2*NB*32];
__device__ float g_alpha[NB*KK];
__device__ float g_A[NB];                 // sum_k alpha[b][k]  (ramp slope)
__device__ float g_u[NB*RR*GG];
__device__ float g_v[NB*RR*GG];
__device__ float g_w[NB*RR*GG];
__device__ float g_c[NB*RR*3];
__device__ float g_norm;
__device__ unsigned int g_rmin[3];        // mapped-uint residual min per channel
__device__ unsigned int g_rmax[3];
__device__ unsigned int g_packed[NB*G3];  // quantized residual LUT (575 KB)

// monotonic float<->uint mapping for atomic min/max
__device__ __forceinline__ unsigned int fmap(float f) {
    unsigned int b = __float_as_uint(f);
    return b ^ (((unsigned int)((int)b >> 31)) | 0x80000000u);
}
__device__ __forceinline__ float funmap(unsigned int m) {
    unsigned int b = (m & 0x80000000u) ? (m ^ 0x80000000u) : ~m;
    return __uint_as_float(b);
}

// ============================================================
// K1: conv1 (3->16, 3x3, stride2, pad1) + relu, both encoders
// ============================================================
__global__ void __launch_bounds__(256) conv1_kernel(
    const float* __restrict__ img_lr,
    const float* __restrict__ w_wp, const float* __restrict__ b_wp,
    const float* __restrict__ w_rp, const float* __restrict__ b_rp)
{
    __shared__ float ws[432];
    __shared__ float bs[16];
    int blk = blockIdx.x;          // 0..511
    int e   = blk >> 8;
    int rem = blk & 255;
    int b   = rem >> 6;
    int tile= rem & 63;
    const float* w  = e ? w_rp : w_wp;
    const float* bi = e ? b_rp : b_wp;
    int tid = threadIdx.x;
    for (int i = tid; i < 432; i += 256) ws[i] = w[i];
    if (tid < 16) bs[tid] = bi[tid];
    if (blk == 0) g_hsum[tid] = 0.f;
    __syncthreads();

    int pix = tile*256 + tid;
    int oh = pix >> 7, ow = pix & 127;
    float in[27];
    #pragma unroll
    for (int ci = 0; ci < 3; ci++)
      #pragma unroll
      for (int kh = 0; kh < 3; kh++)
        #pragma unroll
        for (int kw = 0; kw < 3; kw++) {
            int ih = 2*oh - 1 + kh, iw = 2*ow - 1 + kw;
            float v = 0.f;
            if (ih >= 0 && ih < HL && iw >= 0 && iw < WL)
                v = img_lr[((b*3 + ci)*HL + ih)*WL + iw];
            in[ci*9 + kh*3 + kw] = v;
        }
    float acc[16];
    #pragma unroll
    for (int co = 0; co < 16; co++) acc[co] = bs[co];
    #pragma unroll
    for (int j = 0; j < 27; j++) {
        float v = in[j];
        #pragma unroll
        for (int co = 0; co < 16; co++) acc[co] = fmaf(v, ws[co*27 + j], acc[co]);
    }
    float* outp = g_s1 + (size_t)(e*NB + b)*16*16384 + pix;
    #pragma unroll
    for (int co = 0; co < 16; co++) outp[co*16384] = fmaxf(acc[co], 0.f);
}

// ============================================================
// K2: conv2 (16->32, 3x3, stride2, pad1) + relu + spatial-sum
// ============================================================
__global__ void __launch_bounds__(256) conv2_kernel(
    const float* __restrict__ w_wp, const float* __restrict__ b_wp,
    const float* __restrict__ w_rp, const float* __restrict__ b_rp)
{
    __shared__ float ws[4608];
    __shared__ float bs[32];
    __shared__ float red[8*32];
    int blk = blockIdx.x;
    int e   = blk >> 6;
    int b   = (blk >> 4) & 3;
    int tile= blk & 15;
    const float* w  = e ? w_rp : w_wp;
    const float* bi = e ? b_rp : b_wp;
    int tid = threadIdx.x;
    for (int t = tid; t < 4608; t += 256) {
        int co = t & 31;
        int cik = t >> 5;
        int ci = cik / 9, k = cik - ci*9;
        ws[t] = w[(co*16 + ci)*9 + k];
    }
    if (tid < 32) bs[tid] = bi[tid];
    __syncthreads();

    int pix = tile*256 + tid;
    int oh = pix >> 6, ow = pix & 63;
    const float* inp = g_s1 + (size_t)(e*NB + b)*16*16384;
    float acc[32];
    #pragma unroll
    for (int co = 0; co < 32; co++) acc[co] = 0.f;
    for (int ci = 0; ci < 16; ci++) {
        float v9[9];
        #pragma unroll
        for (int kh = 0; kh < 3; kh++)
          #pragma unroll
          for (int kw = 0; kw < 3; kw++) {
              int ih = 2*oh - 1 + kh, iw = 2*ow - 1 + kw;
              float v = 0.f;
              if (ih >= 0 && ih < 128 && iw >= 0 && iw < 128)
                  v = inp[ci*16384 + ih*128 + iw];
              v9[kh*3 + kw] = v;
          }
        #pragma unroll
        for (int k = 0; k < 9; k++) {
            float v = v9[k];
            const float* wrow = &ws[(ci*9 + k)*32];
            #pragma unroll
            for (int co = 0; co < 32; co++) acc[co] = fmaf(v, wrow[co], acc[co]);
        }
    }
    int lane = tid & 31, wid = tid >> 5;
    #pragma unroll
    for (int co = 0; co < 32; co++) {
        float v = fmaxf(acc[co] + bs[co], 0.f);
        v += __shfl_down_sync(0xffffffffu, v, 16);
        v += __shfl_down_sync(0xffffffffu, v, 8);
        v += __shfl_down_sync(0xffffffffu, v, 4);
        v += __shfl_down_sync(0xffffffffu, v, 2);
        v += __shfl_down_sync(0xffffffffu, v, 1);
        if (lane == 0) red[wid*32 + co] = v;
    }
    __syncthreads();
    if (tid < 32) {
        float s = 0.f;
        #pragma unroll
        for (int w8 = 0; w8 < 8; w8++) s += red[w8*32 + tid];
        atomicAdd(&g_hsum[(e*NB + b)*32 + tid], s);
    }
}

// ============================================================
// K3: FC heads + init of min/max + ramp slopes
// ============================================================
__global__ void fc_kernel(
    const float* __restrict__ wp_fc_w, const float* __restrict__ wp_fc_b,
    const float* __restrict__ fcu_w,  const float* __restrict__ fcu_b,
    const float* __restrict__ fcv_w,  const float* __restrict__ fcv_b,
    const float* __restrict__ fcw_w,  const float* __restrict__ fcw_b,
    const float* __restrict__ fcc_w,  const float* __restrict__ fcc_b,
    float* __restrict__ d_out)
{
    __shared__ float h[2*NB*32];
    __shared__ float sal[NB*KK];
    int tid = threadIdx.x;
    h[tid] = g_hsum[tid] * (1.f/4096.f);
    if (tid == 0) g_norm = 0.f;
    if (tid < 3) { g_rmin[tid] = 0xFFFFFFFFu; g_rmax[tid] = 0u; }
    __syncthreads();

    if (tid < NB*KK) {                        // alpha (wp encoder)
        int b = tid >> 3, k = tid & 7;
        float s = wp_fc_b[k];
        const float* hb = &h[b*32];
        #pragma unroll
        for (int i = 0; i < 32; i++) s = fmaf(hb[i], wp_fc_w[k*32 + i], s);
        g_alpha[tid] = s;
        sal[tid] = s;
        d_out[ALPHA_OFF + tid] = s;
    }
    __syncthreads();
    if (tid < NB) {
        float a = 0.f;
        #pragma unroll
        for (int k = 0; k < KK; k++) a += sal[tid*KK + k];
        g_A[tid] = a;
    }
    for (int j = tid; j < NB*RR*GG; j += 256) {   // u,v,w (rp encoder)
        int b = j / (RR*GG), jj = j - b*(RR*GG);
        const float* hb = &h[(NB + b)*32];
        float su = fcu_b[jj], sv = fcv_b[jj], sw = fcw_b[jj];
        #pragma unroll
        for (int i = 0; i < 32; i++) {
            float hv = hb[i];
            su = fmaf(hv, fcu_w[jj*32 + i], su);
            sv = fmaf(hv, fcv_w[jj*32 + i], sv);
            sw = fmaf(hv, fcw_w[jj*32 + i], sw);
        }
        g_u[j] = su; g_v[j] = sv; g_w[j] = sw;
    }
    for (int j = tid; j < NB*RR*3; j += 256) {    // c
        int b = j / (RR*3), jj = j - b*(RR*3);
        const float* hb = &h[(NB + b)*32];
        float s = fcc_b[jj];
        #pragma unroll
        for (int i = 0; i < 32; i++) s = fmaf(hb[i], fcc_w[jj*32 + i], s);
        g_c[j] = s;
    }
}

// ============================================================
// K4: delta + L + residual min/max. grid (141, 2): y-dim picks batch pair.
// ============================================================
__global__ void __launch_bounds__(256) delta_kernel(
    const float* __restrict__ bases, float* __restrict__ d_out)
{
    __shared__ float su[NB*RR*GG], sv[NB*RR*GG], sw[NB*RR*GG];
    __shared__ float sc[NB*RR*3];
    __shared__ float sa[NB*KK];
    int tid = threadIdx.x;
    for (int i = tid; i < NB*RR*GG; i += 256) {
        su[i] = g_u[i]; sv[i] = g_v[i]; sw[i] = g_w[i];
    }
    if (tid < NB*RR*3) sc[tid] = g_c[tid];
    if (tid < NB*KK)   sa[tid] = g_alpha[tid];
    __syncthreads();

    int n = blockIdx.x*256 + tid;
    int b0 = blockIdx.y*2;                 // batches {b0, b0+1}
    float local = 0.f;
    unsigned int mn0 = 0xFFFFFFFFu, mn1 = 0xFFFFFFFFu, mn2 = 0xFFFFFFFFu;
    unsigned int mx0 = 0u, mx1 = 0u, mx2 = 0u;
    if (n < G3) {
        int x = n / 1089, rem = n - x*1089;
        int y = rem / 33, z = rem - y*33;
        float bb[KK][3];
        #pragma unroll
        for (int k = 0; k < KK; k++) {
            const float* bp = bases + ((size_t)k*G3 + n)*3;
            bb[k][0] = bp[0]; bb[k][1] = bp[1]; bb[k][2] = bp[2];
        }
        #pragma unroll
        for (int bi = 0; bi < 2; bi++) {
            int b = b0 + bi;
            float d0 = 0.f, d1 = 0.f, d2 = 0.f;
            #pragma unroll
            for (int r = 0; r < RR; r++) {
                int o = b*RR + r;
                float p = su[o*GG + x] * sv[o*GG + y] * sw[o*GG + z];
                d0 = fmaf(p, sc[o*3 + 0], d0);
                d1 = fmaf(p, sc[o*3 + 1], d1);
                d2 = fmaf(p, sc[o*3 + 2], d2);
            }
            float l0 = d0, l1 = d1, l2 = d2;
            #pragma unroll
            for (int k = 0; k < KK; k++) {
                float a = sa[b*KK + k];
                l0 = fmaf(a, bb[k][0], l0);
                l1 = fmaf(a, bb[k][1], l1);
                l2 = fmaf(a, bb[k][2], l2);
            }
            size_t off = (size_t)(b*G3 + n)*3;
            d_out[DELTA_OFF + off    ] = d0;
            d_out[DELTA_OFF + off + 1] = d1;
            d_out[DELTA_OFF + off + 2] = d2;
            d_out[L_OFF + off    ] = l0;
            d_out[L_OFF + off + 1] = l1;
            d_out[L_OFF + off + 2] = l2;
            local += fabsf(d0) + fabsf(d1) + fabsf(d2);
            // residual vs ramp A*coord/32
            float a32 = g_A[b] * (1.f/32.f);
            unsigned int r0 = fmap(l0 - a32*(float)x);
            unsigned int r1 = fmap(l1 - a32*(float)y);
            unsigned int r2 = fmap(l2 - a32*(float)z);
            mn0 = min(mn0, r0); mx0 = max(mx0, r0);
            mn1 = min(mn1, r1); mx1 = max(mx1, r1);
            mn2 = min(mn2, r2); mx2 = max(mx2, r2);
        }
    }
    // warp reductions
    #pragma unroll
    for (int s = 16; s > 0; s >>= 1) {
        local += __shfl_down_sync(0xffffffffu, local, s);
        mn0 = min(mn0, __shfl_down_sync(0xffffffffu, mn0, s));
        mn1 = min(mn1, __shfl_down_sync(0xffffffffu, mn1, s));
        mn2 = min(mn2, __shfl_down_sync(0xffffffffu, mn2, s));
        mx0 = max(mx0, __shfl_down_sync(0xffffffffu, mx0, s));
        mx1 = max(mx1, __shfl_down_sync(0xffffffffu, mx1, s));
        mx2 = max(mx2, __shfl_down_sync(0xffffffffu, mx2, s));
    }
    if ((threadIdx.x & 31) == 0) {
        atomicAdd(&g_norm, local);
        atomicMin(&g_rmin[0], mn0); atomicMax(&g_rmax[0], mx0);
        atomicMin(&g_rmin[1], mn1); atomicMax(&g_rmax[1], mx1);
        atomicMin(&g_rmin[2], mn2); atomicMax(&g_rmax[2], mx2);
    }
}

// ============================================================
// K4b: quantize residuals into packed 11/11/10 uint32. grid (141, 4).
// ============================================================
__global__ void __launch_bounds__(256) quant_kernel(const float* __restrict__ d_outL)
{
    int n = blockIdx.x*256 + threadIdx.x;
    int b = blockIdx.y;
    if (n >= G3) return;
    float lo0 = funmap(g_rmin[0]), hi0 = funmap(g_rmax[0]);
    float lo1 = funmap(g_rmin[1]), hi1 = funmap(g_rmax[1]);
    float lo2 = funmap(g_rmin[2]), hi2 = funmap(g_rmax[2]);
    float is0 = 2047.f / fmaxf(hi0 - lo0, 1e-20f);
    float is1 = 2047.f / fmaxf(hi1 - lo1, 1e-20f);
    float is2 = 1023.f / fmaxf(hi2 - lo2, 1e-20f);
    int x = n / 1089, rem = n - x*1089;
    int y = rem / 33, z = rem - y*33;
    float a32 = g_A[b] * (1.f/32.f);
    size_t off = (size_t)(b*G3 + n)*3;
    float r0 = d_outL[off    ] - a32*(float)x;
    float r1 = d_outL[off + 1] - a32*(float)y;
    float r2 = d_outL[off + 2] - a32*(float)z;
    unsigned int q0 = (unsigned int)min(max((int)fmaf(r0 - lo0, is0, 0.5f), 0), 2047);
    unsigned int q1 = (unsigned int)min(max((int)fmaf(r1 - lo1, is1, 0.5f), 0), 2047);
    unsigned int q2 = (unsigned int)min(max((int)fmaf(r2 - lo2, is2, 0.5f), 0), 1023);
    g_packed[b*G3 + n] = (q0 << 21) | (q1 << 10) | q2;
}

// ============================================================
// K5: trilinear LUT apply — packed 32-bit smem LUT, 8 LDS/pixel.
// ============================================================
struct QP { float s0, s1, s2, l0, l1, l2, a32; };

__device__ __forceinline__ void lut1(
    float r, float g, float bb,
    const unsigned int* __restrict__ sm, const QP& qp,
    float& o0, float& o1, float& o2)
{
    float x = fminf(fmaxf(r  * 32.f, 0.f), 32.f - 1e-6f);
    float y = fminf(fmaxf(g  * 32.f, 0.f), 32.f - 1e-6f);
    float z = fminf(fmaxf(bb * 32.f, 0.f), 32.f - 1e-6f);
    int ix = (int)x, iy = (int)y, iz = (int)z;
    float fx = x - (float)ix, fy = y - (float)iy, fz = z - (float)iz;
    int base = (ix*33 + iy)*33 + iz;
    float wx0 = 1.f - fx, wy0 = 1.f - fy, wz0 = 1.f - fz;
    float a00 = wx0*wy0, a01 = wx0*fy, a10 = fx*wy0, a11 = fx*fy;
    float w[8] = { a00*wz0, a00*fz, a01*wz0, a01*fz,
                   a10*wz0, a10*fz, a11*wz0, a11*fz };
    const int off[8] = {0, 1, 33, 34, 1089, 1090, 1122, 1123};
    float s0 = 0.f, s1 = 0.f, s2 = 0.f;
    #pragma unroll
    for (int j = 0; j < 8; j++) {
        unsigned int q = sm[base + off[j]];
        // integer fields placed in fp32 mantissa: value = 2^23 + q  (exact)
        float fr = __uint_as_float(0x4B000000u | (q >> 21));
        float fg = __uint_as_float(0x4B000000u | ((q >> 10) & 0x7FFu));
        float fb = __uint_as_float(0x4B000000u | (q & 0x3FFu));
        s0 = fmaf(w[j], fr, s0);
        s1 = fmaf(w[j], fg, s1);
        s2 = fmaf(w[j], fb, s2);
    }
    // out = lo' + s*step + A/32 * coord   (lo' absorbs the 2^23 offset)
    o0 = fmaf(s0, qp.s0, qp.l0) + qp.a32 * x;
    o1 = fmaf(s1, qp.s1, qp.l1) + qp.a32 * y;
    o2 = fmaf(s2, qp.s2, qp.l2) + qp.a32 * z;
}

__global__ void __launch_bounds__(1024, 1) trilerp_kernel(
    const float* __restrict__ img, float* __restrict__ d_out)
{
    extern __shared__ __align__(16) unsigned int sm[];
    int b  = blockIdx.x / 37;
    int bb = blockIdx.x % 37;
    int tid = threadIdx.x;
    if (blockIdx.x == 0 && tid == 0)
        d_out[NORM_OFF] = g_norm * (1.f / (float)(NB*G3*3));

    const unsigned int* gp = g_packed + (size_t)b*G3;
    for (int n = tid; n < G3; n += 1024) sm[n] = gp[n];

    QP qp;
    {
        float lo0 = funmap(g_rmin[0]), hi0 = funmap(g_rmax[0]);
        float lo1 = funmap(g_rmin[1]), hi1 = funmap(g_rmax[1]);
        float lo2 = funmap(g_rmin[2]), hi2 = funmap(g_rmax[2]);
        qp.s0 = fmaxf(hi0 - lo0, 1e-20f) * (1.f/2047.f);
        qp.s1 = fmaxf(hi1 - lo1, 1e-20f) * (1.f/2047.f);
        qp.s2 = fmaxf(hi2 - lo2, 1e-20f) * (1.f/1023.f);
        qp.l0 = lo0 - 8388608.f * qp.s0;
        qp.l1 = lo1 - 8388608.f * qp.s1;
        qp.l2 = lo2 - 8388608.f * qp.s2;
        qp.a32 = g_A[b] * (1.f/32.f);
    }
    __syncthreads();

    const float4* Rp = (const float4*)(img + (size_t)(b*3 + 0)*NPIX);
    const float4* Gp = (const float4*)(img + (size_t)(b*3 + 1)*NPIX);
    const float4* Bp = (const float4*)(img + (size_t)(b*3 + 2)*NPIX);
    float4* oR = (float4*)(d_out + (size_t)(b*3 + 0)*NPIX);
    float4* oG = (float4*)(d_out + (size_t)(b*3 + 1)*NPIX);
    float4* oB = (float4*)(d_out + (size_t)(b*3 + 2)*NPIX);

    const int NQ = NPIX/4;
    for (int q = bb*1024 + tid; q < NQ; q += 37*1024) {
        float4 r4 = Rp[q], g4 = Gp[q], b4 = Bp[q];
        float4 o0, o1, o2;
        lut1(r4.x, g4.x, b4.x, sm, qp, o0.x, o1.x, o2.x);
        lut1(r4.y, g4.y, b4.y, sm, qp, o0.y, o1.y, o2.y);
        lut1(r4.z, g4.z, b4.z, sm, qp, o0.z, o1.z, o2.z);
        lut1(r4.w, g4.w, b4.w, sm, qp, o0.w, o1.w, o2.w);
        oR[q] = o0; oG[q] = o1; oB[q] = o2;
    }
}

// ============================================================
// launch
// ============================================================
extern "C" void kernel_launch(void* const* d_in, const int* in_sizes, int n_in,
                              void* d_out_v, int out_size)
{
    const float* img_lr   = (const float*)d_in[0];
    const float* img_full = (const float*)d_in[1];
    const float* bases    = (const float*)d_in[2];
    const float* wp_c1_w  = (const float*)d_in[3];
    const float* wp_c1_b  = (const float*)d_in[4];
    const float* wp_c2_w  = (const float*)d_in[5];
    const float* wp_c2_b  = (const float*)d_in[6];
    const float* wp_fc_w  = (const float*)d_in[7];
    const float* wp_fc_b  = (const float*)d_in[8];
    const float* rp_c1_w  = (const float*)d_in[9];
    const float* rp_c1_b  = (const float*)d_in[10];
    const float* rp_c2_w  = (const float*)d_in[11];
    const float* rp_c2_b  = (const float*)d_in[12];
    const float* rp_fcu_w = (const float*)d_in[13];
    const float* rp_fcu_b = (const float*)d_in[14];
    const float* rp_fcv_w = (const float*)d_in[15];
    const float* rp_fcv_b = (const float*)d_in[16];
    const float* rp_fcw_w = (const float*)d_in[17];
    const float* rp_fcw_b = (const float*)d_in[18];
    const float* rp_fcc_w = (const float*)d_in[19];
    const float* rp_fcc_b = (const float*)d_in[20];
    float* d_out = (float*)d_out_v;

    cudaFuncSetAttribute(trilerp_kernel,
                         cudaFuncAttributeMaxDynamicSharedMemorySize, TRI_SMEM);

    conv1_kernel<<<512, 256>>>(img_lr, wp_c1_w, wp_c1_b, rp_c1_w, rp_c1_b);
    conv2_kernel<<<128, 256>>>(wp_c2_w, wp_c2_b, rp_c2_w, rp_c2_b);
    fc_kernel<<<1, 256>>>(wp_fc_w, wp_fc_b,
                          rp_fcu_w, rp_fcu_b, rp_fcv_w, rp_fcv_b,
                          rp_fcw_w, rp_fcw_b, rp_fcc_w, rp_fcc_b, d_out);
    delta_kernel<<<dim3((G3 + 255)/256, 2), 256>>>(bases, d_out);
    quant_kernel<<<dim3((G3 + 255)/256, 4), 256>>>(d_out + L_OFF);
    trilerp_kernel<<<148, 1024, TRI_SMEM>>>(img_full, d_out);
}